// round 8
// baseline (speedup 1.0000x reference)
#include <cuda_runtime.h>
#include <cuda_bf16.h>
#include <cstdint>

#define NN 50000
#define EE 800000
#define DD 512
#define NV4 (DD/4)
#define SLAB ((size_t)512 * 512)

// ---------------- static scratch (no allocations allowed) ----------------
__device__ float g_s1[(size_t)NN * DD];
__device__ float g_s2[(size_t)NN * DD];
__device__ float g_m1[(size_t)NN * DD];
__device__ float g_m2[(size_t)NN * DD];
__device__ float g_l1[(size_t)NN * DD];
__device__ float g_l2[(size_t)NN * DD];
__device__ float g_z[(size_t)4 * NN * DD];  // z planes (plane 0 reused for cat out)
// slots: 0=h 1=s1 2=s2 3=m1 4=m2 5=l1 6=l2 7=aggsum 8=aggmax
__device__ __nv_bfloat16 g_slh[(size_t)9 * NN * DD];
__device__ __nv_bfloat16 g_sll[(size_t)9 * NN * DD];
__device__ __nv_bfloat16 g_bh[44 * SLAB];   // B transposed hi (40 mixed slabs + cat)
__device__ __nv_bfloat16 g_bl[44 * SLAB];   // B transposed lo
__device__ int   g_deg[NN];
__device__ int   g_rowp[NN + 1];
__device__ int   g_cur[NN];
__device__ int   g_csrc[EE];
__device__ float g_invdeg[NN];
__device__ float g_csum[4 * DD];
__device__ float g_csqr[4 * DD];
__device__ float g_scale[4 * DD];
__device__ float g_shift[4 * DD];

// ---------------- PTX helpers (sm_80-generic only) ----------------
__device__ __forceinline__ uint32_t smem_u32(const void* p) {
    uint32_t a;
    asm("{ .reg .u64 t; cvta.to.shared.u64 t, %1; cvt.u32.u64 %0, t; }" : "=r"(a) : "l"(p));
    return a;
}
__device__ __forceinline__ void cp_async16(uint32_t saddr, const void* gaddr, int sz) {
    asm volatile("cp.async.cg.shared.global [%0], [%1], 16, %2;"
                 :: "r"(saddr), "l"(gaddr), "r"(sz));
}
__device__ __forceinline__ void cp_commit() {
    asm volatile("cp.async.commit_group;");
}
template <int N>
__device__ __forceinline__ void cp_wait() {
    asm volatile("cp.async.wait_group %0;" :: "n"(N));
}
__device__ __forceinline__ void ldsm_x4(uint32_t& r0, uint32_t& r1, uint32_t& r2,
                                        uint32_t& r3, uint32_t addr) {
    asm volatile("ldmatrix.sync.aligned.m8n8.x4.shared.b16 {%0,%1,%2,%3}, [%4];"
                 : "=r"(r0), "=r"(r1), "=r"(r2), "=r"(r3) : "r"(addr));
}
__device__ __forceinline__ void mma_bf16(float* c, const uint32_t* a, const uint32_t* b) {
    asm volatile(
        "mma.sync.aligned.m16n8k16.row.col.f32.bf16.bf16.f32 "
        "{%0,%1,%2,%3}, {%4,%5,%6,%7}, {%8,%9}, {%0,%1,%2,%3};"
        : "+f"(c[0]), "+f"(c[1]), "+f"(c[2]), "+f"(c[3])
        : "r"(a[0]), "r"(a[1]), "r"(a[2]), "r"(a[3]), "r"(b[0]), "r"(b[1]));
}

__device__ __forceinline__ void split2(float x, float y, uint32_t& hi, uint32_t& lo) {
    __nv_bfloat162 h = __floats2bfloat162_rn(x, y);
    float rx = x - __bfloat162float(__low2bfloat16(h));
    float ry = y - __bfloat162float(__high2bfloat16(h));
    __nv_bfloat162 l = __floats2bfloat162_rn(rx, ry);
    hi = *(uint32_t*)&h;
    lo = *(uint32_t*)&l;
}

// ---------------- CSR build ----------------
__global__ void k_count(const int* __restrict__ dst, int E) {
    int e = blockIdx.x * blockDim.x + threadIdx.x;
    if (e < E) atomicAdd(&g_deg[dst[e]], 1);
}

__global__ void k_scan(int M) {
    __shared__ int sh[1024];
    __shared__ int running;
    if (threadIdx.x == 0) running = 0;
    __syncthreads();
    for (int base = 0; base < M; base += 1024) {
        int i = base + threadIdx.x;
        int v = (i < M) ? g_deg[i] : 0;
        sh[threadIdx.x] = v;
        __syncthreads();
        for (int off = 1; off < 1024; off <<= 1) {
            int t = 0;
            if ((int)threadIdx.x >= off) t = sh[threadIdx.x - off];
            __syncthreads();
            sh[threadIdx.x] += t;
            __syncthreads();
        }
        int incl = sh[threadIdx.x];
        int excl = running + incl - v;
        if (i < M) {
            g_rowp[i] = excl;
            g_cur[i] = excl;
            g_invdeg[i] = 1.0f / (float)(v > 1 ? v : 1);
        }
        __syncthreads();
        if (threadIdx.x == 0) running += sh[1023];
        __syncthreads();
    }
    if (threadIdx.x == 0) g_rowp[M] = running;
}

__global__ void k_scatter(const int* __restrict__ src, const int* __restrict__ dst, int E) {
    int e = blockIdx.x * blockDim.x + threadIdx.x;
    if (e < E) {
        int d = dst[e];
        int p = atomicAdd(&g_cur[d], 1);
        g_csrc[p] = src[e];
    }
}

// ------- aggregation: one block per node; bf16 hi/lo into slots 7 (sum), 8 (max) -------
__global__ void k_aggregate(const float* __restrict__ X, int M) {
    int nid = blockIdx.x;
    int t = threadIdx.x;
    int beg = g_rowp[nid], end = g_rowp[nid + 1];
    float4 s = make_float4(0.f, 0.f, 0.f, 0.f);
    float4 m = make_float4(-3.4e38f, -3.4e38f, -3.4e38f, -3.4e38f);
    const float4* Xb = (const float4*)X;
    for (int e = beg; e < end; e++) {
        int r = __ldg(&g_csrc[e]);
        float4 v = __ldg(Xb + (size_t)r * NV4 + t);
        s.x += v.x; s.y += v.y; s.z += v.z; s.w += v.w;
        m.x = fmaxf(m.x, v.x); m.y = fmaxf(m.y, v.y);
        m.z = fmaxf(m.z, v.z); m.w = fmaxf(m.w, v.w);
    }
    if (beg == end) m = make_float4(0.f, 0.f, 0.f, 0.f);
    size_t base = (size_t)nid * 256 + t * 2;  // in bf16x2 units
    uint32_t* sh1 = (uint32_t*)(g_slh + (size_t)7 * NN * DD);
    uint32_t* sl1 = (uint32_t*)(g_sll + (size_t)7 * NN * DD);
    uint32_t* sh2 = (uint32_t*)(g_slh + (size_t)8 * NN * DD);
    uint32_t* sl2 = (uint32_t*)(g_sll + (size_t)8 * NN * DD);
    uint32_t h, l;
    split2(s.x, s.y, h, l); sh1[base] = h; sl1[base] = l;
    split2(s.z, s.w, h, l); sh1[base + 1] = h; sl1[base + 1] = l;
    split2(m.x, m.y, h, l); sh2[base] = h; sl2[base] = l;
    split2(m.z, m.w, h, l); sh2[base + 1] = h; sl2[base + 1] = l;
}

// ---------------- split fp32 state into bf16 hi/lo slot ----------------
__global__ void k_split(const float* __restrict__ X, int slot, int M) {
    int idx = blockIdx.x * blockDim.x + threadIdx.x;
    int total = M * NV4;
    if (idx >= total) return;
    float4 v = ((const float4*)X)[idx];
    uint32_t* sh = (uint32_t*)(g_slh + (size_t)slot * NN * DD);
    uint32_t* sl = (uint32_t*)(g_sll + (size_t)slot * NN * DD);
    uint32_t h, l;
    split2(v.x, v.y, h, l); sh[idx * 2] = h; sl[idx * 2] = l;
    split2(v.z, v.w, h, l); sh[idx * 2 + 1] = h; sl[idx * 2 + 1] = l;
}

// ------ weight prep: transpose [K][N]->[N][K] + bf16 hi/lo split ------
__global__ void k_prep(const float* __restrict__ W, size_t dofs, int K, int N) {
    __shared__ float t[32][33];
    const float* Wp = W + (size_t)blockIdx.z * K * N;
    __nv_bfloat16* oh = g_bh + dofs + (size_t)blockIdx.z * K * N;
    __nv_bfloat16* ol = g_bl + dofs + (size_t)blockIdx.z * K * N;
    int k0 = blockIdx.x * 32;
    int n0 = blockIdx.y * 32;
    int tx = threadIdx.x & 31, ty = threadIdx.x >> 5;
    for (int r = ty; r < 32; r += 8)
        t[r][tx] = __ldg(Wp + (size_t)(k0 + r) * N + n0 + tx);
    __syncthreads();
    for (int r = ty; r < 32; r += 8) {
        float w = t[tx][r];
        __nv_bfloat16 hb = __float2bfloat16_rn(w);
        float lof = w - __bfloat162float(hb);
        size_t o = (size_t)(n0 + r) * K + k0 + tx;
        oh[o] = hb;
        ol[o] = __float2bfloat16_rn(lof);
    }
}

// ---------------- bf16x3 mma.sync GEMM ----------------
// CTA 128x256, 16 warps (4m x 4n), warp 32x64, BK=32 double-buffered cp.async.
// mode 0: z[plane] = A_slot @ B[bofs + plane*SLAB] (K=512), plane=blockIdx.z
//         A slot: plane0 -> aslot, planes 1,2 -> 7 (sum), plane3 -> 8 (max)
// mode 1: z[0] = [slot3|slot4|slot5|slot6] @ B[bofs] (K=2048)
#define APLANE 10240                       // 128 rows * 80B
#define BPLANE 20480                       // 256 rows * 80B
#define STAGEB (2 * APLANE + 2 * BPLANE)   // 61440
#define SMEM_GEMM (2 * STAGEB)             // 122880

__global__ void __launch_bounds__(512, 1)
k_gemm_mma(const float* __restrict__ bias, int M, int mode, int aslot, size_t bofs) {
    extern __shared__ char smem[];
    uint32_t sbase = smem_u32(smem);
    const int tid = threadIdx.x;
    const int wid = tid >> 5, lane = tid & 31;
    const int wm = wid & 3, wn = wid >> 2;
    const int rowBase = blockIdx.x * 128;
    const int colBase = blockIdx.y * 256;
    const int plane = blockIdx.z;

    const int K = (mode == 0) ? 512 : 2048;
    const int nStages = K / 32;
    const int bK = K;
    const size_t bOff = bofs + ((mode == 0) ? (size_t)plane * SLAB : 0);

    auto loadA = [&](int s) {
        int slot, kin;
        if (mode == 0) {
            slot = (plane == 0) ? aslot : ((plane == 3) ? 8 : 7);
            kin = s * 32;
        } else {
            slot = 3 + (s >> 4);
            kin = (s & 15) * 32;
        }
        const __nv_bfloat16* aH = g_slh + (size_t)slot * NN * DD;
        const __nv_bfloat16* aL = g_sll + (size_t)slot * NN * DD;
#pragma unroll
        for (int i = 0; i < 2; i++) {
            int idx = tid + 512 * i;
            int pl = idx >> 9, r = (idx >> 2) & 127, ch = idx & 3;
            int grow = rowBase + r;
            int gr = (grow < M) ? grow : (M - 1);
            const __nv_bfloat16* gp = (pl ? aL : aH) + (size_t)gr * 512 + kin + ch * 8;
            uint32_t dst = sbase + (s & 1) * STAGEB + pl * APLANE + r * 80 + ch * 16;
            cp_async16(dst, gp, (grow < M) ? 16 : 0);
        }
    };
    auto loadB = [&](int s) {
        int kin = s * 32;
#pragma unroll
        for (int i = 0; i < 4; i++) {
            int idx = tid + 512 * i;
            int pl = idx >> 10, r = (idx >> 2) & 255, ch = idx & 3;
            const __nv_bfloat16* gp =
                (pl ? g_bl : g_bh) + bOff + (size_t)(colBase + r) * bK + kin + ch * 8;
            uint32_t dst = sbase + (s & 1) * STAGEB + 2 * APLANE + pl * BPLANE + r * 80 + ch * 16;
            cp_async16(dst, gp, 16);
        }
    };

    float c[2][8][4];
#pragma unroll
    for (int mi = 0; mi < 2; mi++)
#pragma unroll
        for (int ni = 0; ni < 8; ni++)
#pragma unroll
            for (int j = 0; j < 4; j++) c[mi][ni][j] = 0.f;

    loadA(0); loadB(0); cp_commit();
    loadA(1); loadB(1); cp_commit();

    for (int s = 0; s < nStages; s++) {
        if (s + 1 < nStages) cp_wait<1>(); else cp_wait<0>();
        __syncthreads();
        uint32_t stg = sbase + (s & 1) * STAGEB;
        uint32_t aHiB = stg, aLoB = stg + APLANE;
        uint32_t bHiB = stg + 2 * APLANE, bLoB = bHiB + BPLANE;
#pragma unroll
        for (int kc = 0; kc < 2; kc++) {
            uint32_t ah[2][4], al[2][4];
#pragma unroll
            for (int mi = 0; mi < 2; mi++) {
                int row = wm * 32 + mi * 16 + (lane & 15);
                uint32_t off = (uint32_t)row * 80 + kc * 32 + (lane >> 4) * 16;
                ldsm_x4(ah[mi][0], ah[mi][1], ah[mi][2], ah[mi][3], aHiB + off);
                ldsm_x4(al[mi][0], al[mi][1], al[mi][2], al[mi][3], aLoB + off);
            }
            // np-pair blocks; within a block issue pass-major (hh, lh, hl) over
            // 8 independent accumulators -> dependent-reuse distance 8.
#pragma unroll
            for (int half = 0; half < 2; half++) {
                uint32_t bt[4][2], cl[4][2];
#pragma unroll
                for (int p = 0; p < 2; p++) {
                    int np = half * 2 + p;
                    int n = wn * 64 + np * 16 + ((lane >> 4) << 3) + (lane & 7);
                    uint32_t off = (uint32_t)n * 80 + kc * 32 + ((lane >> 3) & 1) * 16;
                    uint32_t h0, h1, h2, h3, l0, l1, l2, l3;
                    ldsm_x4(h0, h1, h2, h3, bHiB + off);
                    ldsm_x4(l0, l1, l2, l3, bLoB + off);
                    bt[2 * p][0] = h0; bt[2 * p][1] = h1;
                    bt[2 * p + 1][0] = h2; bt[2 * p + 1][1] = h3;
                    cl[2 * p][0] = l0; cl[2 * p][1] = l1;
                    cl[2 * p + 1][0] = l2; cl[2 * p + 1][1] = l3;
                }
#pragma unroll
                for (int t = 0; t < 4; t++)
#pragma unroll
                    for (int mi = 0; mi < 2; mi++)
                        mma_bf16(c[mi][half * 4 + t], ah[mi], bt[t]);
#pragma unroll
                for (int t = 0; t < 4; t++)
#pragma unroll
                    for (int mi = 0; mi < 2; mi++)
                        mma_bf16(c[mi][half * 4 + t], al[mi], bt[t]);
#pragma unroll
                for (int t = 0; t < 4; t++)
#pragma unroll
                    for (int mi = 0; mi < 2; mi++)
                        mma_bf16(c[mi][half * 4 + t], ah[mi], cl[t]);
            }
        }
        __syncthreads();
        if (s + 2 < nStages) { loadA(s + 2); loadB(s + 2); cp_commit(); }
    }

    // ---- epilogue ----
    const float* bp = bias + ((mode == 0) ? plane * DD : 0);
    float* zbase = (mode == 0) ? (g_z + (size_t)plane * M * DD) : g_z;
    const int doScale = (mode == 0 && plane == 2);
#pragma unroll
    for (int mi = 0; mi < 2; mi++) {
        int row0 = rowBase + wm * 32 + mi * 16 + (lane >> 2);
        int row1 = row0 + 8;
        float rs0 = 1.f, rs1 = 1.f;
        if (doScale) {
            if (row0 < M) rs0 = g_invdeg[row0];
            if (row1 < M) rs1 = g_invdeg[row1];
        }
#pragma unroll
        for (int ni = 0; ni < 8; ni++) {
            int col = colBase + wn * 64 + ni * 8 + (lane & 3) * 2;
            float b0 = __ldg(bp + col), b1 = __ldg(bp + col + 1);
            if (row0 < M) {
                float2 v;
                v.x = fmaf(c[mi][ni][0], rs0, b0);
                v.y = fmaf(c[mi][ni][1], rs0, b1);
                *(float2*)(zbase + (size_t)row0 * DD + col) = v;
            }
            if (row1 < M) {
                float2 v;
                v.x = fmaf(c[mi][ni][2], rs1, b0);
                v.y = fmaf(c[mi][ni][3], rs1, b1);
                *(float2*)(zbase + (size_t)row1 * DD + col) = v;
            }
        }
    }
}

// ---------------- per-(k,d) stats over nodes ----------------
__global__ void k_stats(int M) {
    int k = blockIdx.x >> 2;
    int d = ((blockIdx.x & 3) << 7) + threadIdx.x;
    int rows = (M + gridDim.y - 1) / gridDim.y;
    int r0 = blockIdx.y * rows;
    int r1 = r0 + rows; if (r1 > M) r1 = M;
    const float* p = g_z + ((size_t)k * M) * DD + d;
    float s = 0.f, q = 0.f;
    for (int r = r0; r < r1; r++) {
        float v = __ldg(p + (size_t)r * DD);
        s += v;
        q = fmaf(v, v, q);
    }
    atomicAdd(&g_csum[k * DD + d], s);
    atomicAdd(&g_csqr[k * DD + d], q);
}

__global__ void k_finalize(const float* __restrict__ gam, const float* __restrict__ bet,
                           int M, int P) {
    int i = blockIdx.x * blockDim.x + threadIdx.x;
    if (i < P * DD) {
        float inv = 1.0f / (float)M;
        float mu = g_csum[i] * inv;
        float var = g_csqr[i] * inv - mu * mu;
        float sc = rsqrtf(var + 1e-5f) * gam[i];
        g_scale[i] = sc;
        g_shift[i] = bet[i] - mu * sc;
    }
}

// ------- weighted relu combine over k (+ fused bf16 hi/lo split of result) -------
__global__ void k_combine(const float* __restrict__ w, float* __restrict__ out,
                          int M, int acc, int slot, int doSplit) {
    int idx = blockIdx.x * blockDim.x + threadIdx.x;
    int total = M * NV4;
    if (idx >= total) return;
    int dc = (idx % NV4) * 4;
    float4 r = acc ? ((const float4*)out)[idx] : make_float4(0.f, 0.f, 0.f, 0.f);
#pragma unroll
    for (int k = 0; k < 4; k++) {
        float wk = __ldg(w + k);
        float4 v = __ldg((const float4*)g_z + (size_t)k * M * NV4 + idx);
        float4 sc = *(const float4*)&g_scale[k * DD + dc];
        float4 sh = *(const float4*)&g_shift[k * DD + dc];
        float e;
        e = fmaxf(fmaf(v.x, sc.x, sh.x), 0.f); r.x = fmaf(wk, e, r.x);
        e = fmaxf(fmaf(v.y, sc.y, sh.y), 0.f); r.y = fmaf(wk, e, r.y);
        e = fmaxf(fmaf(v.z, sc.z, sh.z), 0.f); r.z = fmaf(wk, e, r.z);
        e = fmaxf(fmaf(v.w, sc.w, sh.w), 0.f); r.w = fmaf(wk, e, r.w);
    }
    ((float4*)out)[idx] = r;
    if (doSplit) {
        uint32_t* sh = (uint32_t*)(g_slh + (size_t)slot * NN * DD);
        uint32_t* sl = (uint32_t*)(g_sll + (size_t)slot * NN * DD);
        uint32_t h, l;
        split2(r.x, r.y, h, l); sh[idx * 2] = h; sl[idx * 2] = l;
        split2(r.z, r.w, h, l); sh[idx * 2 + 1] = h; sl[idx * 2 + 1] = l;
    }
}

// ---------------- final residual + BN + relu ----------------
__global__ void k_final(const float* __restrict__ h, float* __restrict__ out, int M) {
    int idx = blockIdx.x * blockDim.x + threadIdx.x;
    int total = M * NV4;
    if (idx >= total) return;
    int dc = (idx % NV4) * 4;
    float4 v = ((const float4*)g_z)[idx];
    float4 sc = *(const float4*)&g_scale[dc];
    float4 sh = *(const float4*)&g_shift[dc];
    float4 hv = ((const float4*)h)[idx];
    float4 o;
    o.x = hv.x + fmaxf(fmaf(v.x, sc.x, sh.x), 0.f);
    o.y = hv.y + fmaxf(fmaf(v.y, sc.y, sh.y), 0.f);
    o.z = hv.z + fmaxf(fmaf(v.z, sc.z, sh.z), 0.f);
    o.w = hv.w + fmaxf(fmaf(v.w, sc.w, sh.w), 0.f);
    ((float4*)out)[idx] = o;
}

// ---------------- host orchestration ----------------
static void run_mixed(int wslab, const float* b4, const float* g4, const float* be4,
                      const float* w4, int inSlot, float* outp, int acc,
                      int outSlot, int doSplit, int M, void* sump, void* sqrp) {
    cudaMemsetAsync(sump, 0, 4 * DD * sizeof(float));
    cudaMemsetAsync(sqrp, 0, 4 * DD * sizeof(float));
    k_gemm_mma<<<dim3((M + 127) / 128, 2, 4), 512, SMEM_GEMM>>>(
        b4, M, 0, inSlot, (size_t)wslab * SLAB);
    k_stats<<<dim3(16, 128), 128>>>(M);
    k_finalize<<<8, 256>>>(g4, be4, M, 4);
    k_combine<<<(M * NV4 + 255) / 256, 256>>>(w4, outp, M, acc, outSlot, doSplit);
}

extern "C" void kernel_launch(void* const* d_in, const int* in_sizes, int n_in,
                              void* d_out, int out_size) {
    const float* h    = (const float*)d_in[0];
    const int*   src  = (const int*)d_in[1];
    const int*   dst  = (const int*)d_in[2];
    const float* wf   = (const float*)d_in[3];
    const float* wm   = (const float*)d_in[4];
    const float* wl   = (const float*)d_in[5];
    const float* pfW  = (const float*)d_in[6];
    const float* pfb  = (const float*)d_in[7];
    const float* pfg  = (const float*)d_in[8];
    const float* pfB  = (const float*)d_in[9];
    const float* pmW  = (const float*)d_in[10];
    const float* pmb  = (const float*)d_in[11];
    const float* pmg  = (const float*)d_in[12];
    const float* pmB  = (const float*)d_in[13];
    const float* plW  = (const float*)d_in[14];
    const float* plb  = (const float*)d_in[15];
    const float* plg  = (const float*)d_in[16];
    const float* plB  = (const float*)d_in[17];
    const float* catW = (const float*)d_in[18];
    const float* catb = (const float*)d_in[19];
    const float* bng  = (const float*)d_in[20];
    const float* bnb  = (const float*)d_in[21];

    int M = in_sizes[0] / DD;
    int E = in_sizes[1];
    float* out = (float*)d_out;

    cudaFuncSetAttribute(k_gemm_mma, cudaFuncAttributeMaxDynamicSharedMemorySize, SMEM_GEMM);

    void *s1, *s2, *m1, *m2, *l1, *l2, *degp, *sump, *sqrp;
    cudaGetSymbolAddress(&s1, g_s1);
    cudaGetSymbolAddress(&s2, g_s2);
    cudaGetSymbolAddress(&m1, g_m1);
    cudaGetSymbolAddress(&m2, g_m2);
    cudaGetSymbolAddress(&l1, g_l1);
    cudaGetSymbolAddress(&l2, g_l2);
    cudaGetSymbolAddress(&degp, g_deg);
    cudaGetSymbolAddress(&sump, g_csum);
    cudaGetSymbolAddress(&sqrp, g_csqr);

    const size_t slabB = 4 * DD;
    const int nsp = (M * NV4 + 255) / 256;

    // ---- all weight prep up front (4 launches) ----
    k_prep<<<dim3(16, 16, 12), 256>>>(pfW, 0, 512, 512);
    k_prep<<<dim3(16, 16, 8), 256>>>(pmW, 12 * SLAB, 512, 512);
    k_prep<<<dim3(16, 16, 20), 256>>>(plW, 20 * SLAB, 512, 512);
    k_prep<<<dim3(64, 16, 1), 256>>>(catW, 40 * SLAB, 2048, 512);

    // CSR build (shared by all aggregations this launch)
    cudaMemsetAsync(degp, 0, M * sizeof(int));
    k_count<<<(E + 255) / 256, 256>>>(dst, E);
    k_scan<<<1, 1024>>>(M);
    k_scatter<<<(E + 255) / 256, 256>>>(src, dst, E);

    // first block: s1 = mixed(wf0, h); s2 = mixed(wf1, h) + mixed(wf2, s1)
    k_aggregate<<<M, 128>>>(h, M);
    k_split<<<nsp, 256>>>(h, 0, M);
    run_mixed(0, pfb + 0 * slabB, pfg + 0 * slabB, pfB + 0 * slabB, wf + 0,
              0, (float*)s1, 0, 1, 1, M, sump, sqrp);
    run_mixed(4, pfb + 1 * slabB, pfg + 1 * slabB, pfB + 1 * slabB, wf + 4,
              0, (float*)s2, 0, 2, 0, M, sump, sqrp);
    k_aggregate<<<M, 128>>>((const float*)s1, M);
    run_mixed(8, pfb + 2 * slabB, pfg + 2 * slabB, pfB + 2 * slabB, wf + 8,
              1, (float*)s2, 1, 2, 1, M, sump, sqrp);
    // middle (agg(s1) still in slots 7/8): m1 = mixed(wm0, s1)
    run_mixed(12, pmb + 0 * slabB, pmg + 0 * slabB, pmB + 0 * slabB, wm + 0,
              1, (float*)m1, 0, 3, 1, M, sump, sqrp);
    k_aggregate<<<M, 128>>>((const float*)s2, M);
    run_mixed(16, pmb + 1 * slabB, pmg + 1 * slabB, pmB + 1 * slabB, wm + 4,
              2, (float*)m2, 0, 4, 1, M, sump, sqrp);
    // last block: l1 = mixed(wl0,m1)+mixed(wl1,m2); l2 = mixed(wl2,m1)+mixed(wl3,m2)+mixed(wl4,l1)
    k_aggregate<<<M, 128>>>((const float*)m1, M);
    run_mixed(20, plb + 0 * slabB, plg + 0 * slabB, plB + 0 * slabB, wl + 0,
              3, (float*)l1, 0, 5, 0, M, sump, sqrp);
    run_mixed(28, plb + 2 * slabB, plg + 2 * slabB, plB + 2 * slabB, wl + 8,
              3, (float*)l2, 0, 6, 0, M, sump, sqrp);
    k_aggregate<<<M, 128>>>((const float*)m2, M);
    run_mixed(24, plb + 1 * slabB, plg + 1 * slabB, plB + 1 * slabB, wl + 4,
              4, (float*)l1, 1, 5, 1, M, sump, sqrp);
    run_mixed(32, plb + 3 * slabB, plg + 3 * slabB, plB + 3 * slabB, wl + 12,
              4, (float*)l2, 1, 6, 0, M, sump, sqrp);
    k_aggregate<<<M, 128>>>((const float*)l1, M);
    run_mixed(36, plb + 4 * slabB, plg + 4 * slabB, plB + 4 * slabB, wl + 16,
              5, (float*)l2, 1, 6, 1, M, sump, sqrp);

    // cat GEMM + batchnorm + relu + residual
    k_gemm_mma<<<dim3((M + 127) / 128, 2, 1), 512, SMEM_GEMM>>>(
        catb, M, 1, 0, (size_t)40 * SLAB);
    cudaMemsetAsync(sump, 0, 4 * DD * sizeof(float));
    cudaMemsetAsync(sqrp, 0, 4 * DD * sizeof(float));
    k_stats<<<dim3(4, 128), 128>>>(M);
    k_finalize<<<8, 256>>>(bng, bnb, M, 1);
    k_final<<<nsp, 256>>>(h, out, M);
}

// round 10
// speedup vs baseline: 1.0101x; 1.0101x over previous
#include <cuda_runtime.h>
#include <cuda_bf16.h>
#include <cstdint>

#define NN 50000
#define EE 800000
#define DD 512
#define NV4 (DD/4)
#define SLAB ((size_t)512 * 512)

// ---------------- static scratch (no allocations allowed) ----------------
__device__ float g_s1[(size_t)NN * DD];
__device__ float g_s2[(size_t)NN * DD];
__device__ float g_m1[(size_t)NN * DD];
__device__ float g_m2[(size_t)NN * DD];
__device__ float g_l1[(size_t)NN * DD];
__device__ float g_l2[(size_t)NN * DD];
__device__ float g_z[(size_t)4 * NN * DD];  // z planes (plane 0 reused for cat out)
// slots: 0=h 1=s1 2=s2 3=m1 4=m2 5=l1 6=l2 7=aggsum 8=aggmax
__device__ __nv_bfloat16 g_slh[(size_t)9 * NN * DD];
__device__ __nv_bfloat16 g_sll[(size_t)9 * NN * DD];
__device__ __nv_bfloat16 g_bh[44 * SLAB];   // B transposed hi (40 mixed slabs + cat)
__device__ __nv_bfloat16 g_bl[44 * SLAB];   // B transposed lo
__device__ int   g_deg[NN];
__device__ int   g_rowp[NN + 1];
__device__ int   g_cur[NN];
__device__ int   g_csrc[EE];
__device__ float g_invdeg[NN];
__device__ float g_csum[4 * DD];
__device__ float g_csqr[4 * DD];
__device__ float g_scale[4 * DD];
__device__ float g_shift[4 * DD];

// ---------------- PTX helpers (sm_80-generic only) ----------------
__device__ __forceinline__ uint32_t smem_u32(const void* p) {
    uint32_t a;
    asm("{ .reg .u64 t; cvta.to.shared.u64 t, %1; cvt.u32.u64 %0, t; }" : "=r"(a) : "l"(p));
    return a;
}
__device__ __forceinline__ void cp_async16(uint32_t saddr, const void* gaddr, int sz) {
    asm volatile("cp.async.cg.shared.global [%0], [%1], 16, %2;"
                 :: "r"(saddr), "l"(gaddr), "r"(sz));
}
__device__ __forceinline__ void cp_commit() {
    asm volatile("cp.async.commit_group;");
}
template <int N>
__device__ __forceinline__ void cp_wait() {
    asm volatile("cp.async.wait_group %0;" :: "n"(N));
}
__device__ __forceinline__ void ldsm_x4(uint32_t& r0, uint32_t& r1, uint32_t& r2,
                                        uint32_t& r3, uint32_t addr) {
    asm volatile("ldmatrix.sync.aligned.m8n8.x4.shared.b16 {%0,%1,%2,%3}, [%4];"
                 : "=r"(r0), "=r"(r1), "=r"(r2), "=r"(r3) : "r"(addr));
}
__device__ __forceinline__ void mma_bf16(float* c, const uint32_t* a, const uint32_t* b) {
    asm volatile(
        "mma.sync.aligned.m16n8k16.row.col.f32.bf16.bf16.f32 "
        "{%0,%1,%2,%3}, {%4,%5,%6,%7}, {%8,%9}, {%0,%1,%2,%3};"
        : "+f"(c[0]), "+f"(c[1]), "+f"(c[2]), "+f"(c[3])
        : "r"(a[0]), "r"(a[1]), "r"(a[2]), "r"(a[3]), "r"(b[0]), "r"(b[1]));
}

__device__ __forceinline__ void split2(float x, float y, uint32_t& hi, uint32_t& lo) {
    __nv_bfloat162 h = __floats2bfloat162_rn(x, y);
    float rx = x - __bfloat162float(__low2bfloat16(h));
    float ry = y - __bfloat162float(__high2bfloat16(h));
    __nv_bfloat162 l = __floats2bfloat162_rn(rx, ry);
    hi = *(uint32_t*)&h;
    lo = *(uint32_t*)&l;
}

// ---------------- CSR build ----------------
__global__ void k_count(const int* __restrict__ dst, int E) {
    int e = blockIdx.x * blockDim.x + threadIdx.x;
    if (e < E) atomicAdd(&g_deg[dst[e]], 1);
}

__global__ void k_scan(int M) {
    __shared__ int sh[1024];
    __shared__ int running;
    if (threadIdx.x == 0) running = 0;
    __syncthreads();
    for (int base = 0; base < M; base += 1024) {
        int i = base + threadIdx.x;
        int v = (i < M) ? g_deg[i] : 0;
        sh[threadIdx.x] = v;
        __syncthreads();
        for (int off = 1; off < 1024; off <<= 1) {
            int t = 0;
            if ((int)threadIdx.x >= off) t = sh[threadIdx.x - off];
            __syncthreads();
            sh[threadIdx.x] += t;
            __syncthreads();
        }
        int incl = sh[threadIdx.x];
        int excl = running + incl - v;
        if (i < M) {
            g_rowp[i] = excl;
            g_cur[i] = excl;
            g_invdeg[i] = 1.0f / (float)(v > 1 ? v : 1);
        }
        __syncthreads();
        if (threadIdx.x == 0) running += sh[1023];
        __syncthreads();
    }
    if (threadIdx.x == 0) g_rowp[M] = running;
}

__global__ void k_scatter(const int* __restrict__ src, const int* __restrict__ dst, int E) {
    int e = blockIdx.x * blockDim.x + threadIdx.x;
    if (e < E) {
        int d = dst[e];
        int p = atomicAdd(&g_cur[d], 1);
        g_csrc[p] = src[e];
    }
}

// ------- aggregation: one block per node; bf16 hi/lo into slots 7 (sum), 8 (max) -------
__global__ void k_aggregate(const float* __restrict__ X, int M) {
    int nid = blockIdx.x;
    int t = threadIdx.x;
    int beg = g_rowp[nid], end = g_rowp[nid + 1];
    float4 s = make_float4(0.f, 0.f, 0.f, 0.f);
    float4 m = make_float4(-3.4e38f, -3.4e38f, -3.4e38f, -3.4e38f);
    const float4* Xb = (const float4*)X;
    for (int e = beg; e < end; e++) {
        int r = __ldg(&g_csrc[e]);
        float4 v = __ldg(Xb + (size_t)r * NV4 + t);
        s.x += v.x; s.y += v.y; s.z += v.z; s.w += v.w;
        m.x = fmaxf(m.x, v.x); m.y = fmaxf(m.y, v.y);
        m.z = fmaxf(m.z, v.z); m.w = fmaxf(m.w, v.w);
    }
    if (beg == end) m = make_float4(0.f, 0.f, 0.f, 0.f);
    size_t base = (size_t)nid * 256 + t * 2;  // in bf16x2 units
    uint32_t* sh1 = (uint32_t*)(g_slh + (size_t)7 * NN * DD);
    uint32_t* sl1 = (uint32_t*)(g_sll + (size_t)7 * NN * DD);
    uint32_t* sh2 = (uint32_t*)(g_slh + (size_t)8 * NN * DD);
    uint32_t* sl2 = (uint32_t*)(g_sll + (size_t)8 * NN * DD);
    uint32_t h, l;
    split2(s.x, s.y, h, l); sh1[base] = h; sl1[base] = l;
    split2(s.z, s.w, h, l); sh1[base + 1] = h; sl1[base + 1] = l;
    split2(m.x, m.y, h, l); sh2[base] = h; sl2[base] = l;
    split2(m.z, m.w, h, l); sh2[base + 1] = h; sl2[base + 1] = l;
}

// ---------------- split fp32 state into bf16 hi/lo slot ----------------
__global__ void k_split(const float* __restrict__ X, int slot, int M) {
    int idx = blockIdx.x * blockDim.x + threadIdx.x;
    int total = M * NV4;
    if (idx >= total) return;
    float4 v = ((const float4*)X)[idx];
    uint32_t* sh = (uint32_t*)(g_slh + (size_t)slot * NN * DD);
    uint32_t* sl = (uint32_t*)(g_sll + (size_t)slot * NN * DD);
    uint32_t h, l;
    split2(v.x, v.y, h, l); sh[idx * 2] = h; sl[idx * 2] = l;
    split2(v.z, v.w, h, l); sh[idx * 2 + 1] = h; sl[idx * 2 + 1] = l;
}

// ------ weight prep: transpose [K][N]->[N][K] + bf16 hi/lo split ------
__global__ void k_prep(const float* __restrict__ W, size_t dofs, int K, int N) {
    __shared__ float t[32][33];
    const float* Wp = W + (size_t)blockIdx.z * K * N;
    __nv_bfloat16* oh = g_bh + dofs + (size_t)blockIdx.z * K * N;
    __nv_bfloat16* ol = g_bl + dofs + (size_t)blockIdx.z * K * N;
    int k0 = blockIdx.x * 32;
    int n0 = blockIdx.y * 32;
    int tx = threadIdx.x & 31, ty = threadIdx.x >> 5;
    for (int r = ty; r < 32; r += 8)
        t[r][tx] = __ldg(Wp + (size_t)(k0 + r) * N + n0 + tx);
    __syncthreads();
    for (int r = ty; r < 32; r += 8) {
        float w = t[tx][r];
        __nv_bfloat16 hb = __float2bfloat16_rn(w);
        float lof = w - __bfloat162float(hb);
        size_t o = (size_t)(n0 + r) * K + k0 + tx;
        oh[o] = hb;
        ol[o] = __float2bfloat16_rn(lof);
    }
}

// ---------------- bf16x3 mma.sync GEMM (+ fused BN stats in epilogue) ----------------
// CTA 128x256, 16 warps (4m x 4n), warp 32x64, BK=32, 3-stage cp.async pipeline.
// mode 0: z[plane] = A_slot @ B[bofs + plane*SLAB] (K=512), plane=blockIdx.z
//         A slot: plane0 -> aslot, planes 1,2 -> 7 (sum), plane3 -> 8 (max)
// mode 1: z[0] = [slot3|slot4|slot5|slot6] @ B[bofs] (K=2048)
#define APLANE 10240                       // 128 rows * 80B
#define BPLANE 20480                       // 256 rows * 80B
#define STAGEB (2 * APLANE + 2 * BPLANE)   // 61440
#define SMEM_GEMM (3 * STAGEB)             // 184320

__global__ void __launch_bounds__(512, 1)
k_gemm_mma(const float* __restrict__ bias, int M, int mode, int aslot, size_t bofs) {
    extern __shared__ char smem[];
    uint32_t sbase = smem_u32(smem);
    const int tid = threadIdx.x;
    const int wid = tid >> 5, lane = tid & 31;
    const int wm = wid & 3, wn = wid >> 2;
    const int rowBase = blockIdx.x * 128;
    const int colBase = blockIdx.y * 256;
    const int plane = blockIdx.z;

    const int K = (mode == 0) ? 512 : 2048;
    const int nStages = K / 32;
    const int bK = K;
    const size_t bOff = bofs + ((mode == 0) ? (size_t)plane * SLAB : 0);

    auto loadA = [&](int s) {
        int slot, kin;
        if (mode == 0) {
            slot = (plane == 0) ? aslot : ((plane == 3) ? 8 : 7);
            kin = s * 32;
        } else {
            slot = 3 + (s >> 4);
            kin = (s & 15) * 32;
        }
        const __nv_bfloat16* aH = g_slh + (size_t)slot * NN * DD;
        const __nv_bfloat16* aL = g_sll + (size_t)slot * NN * DD;
        uint32_t stg = sbase + (uint32_t)(s % 3) * STAGEB;
#pragma unroll
        for (int i = 0; i < 2; i++) {
            int idx = tid + 512 * i;
            int pl = idx >> 9, r = (idx >> 2) & 127, ch = idx & 3;
            int grow = rowBase + r;
            int gr = (grow < M) ? grow : (M - 1);
            const __nv_bfloat16* gp = (pl ? aL : aH) + (size_t)gr * 512 + kin + ch * 8;
            uint32_t dst = stg + pl * APLANE + r * 80 + ch * 16;
            cp_async16(dst, gp, (grow < M) ? 16 : 0);
        }
    };
    auto loadB = [&](int s) {
        int kin = s * 32;
        uint32_t stg = sbase + (uint32_t)(s % 3) * STAGEB + 2 * APLANE;
#pragma unroll
        for (int i = 0; i < 4; i++) {
            int idx = tid + 512 * i;
            int pl = idx >> 10, r = (idx >> 2) & 255, ch = idx & 3;
            const __nv_bfloat16* gp =
                (pl ? g_bl : g_bh) + bOff + (size_t)(colBase + r) * bK + kin + ch * 8;
            uint32_t dst = stg + pl * BPLANE + r * 80 + ch * 16;
            cp_async16(dst, gp, 16);
        }
    };

    float c[2][8][4];
#pragma unroll
    for (int mi = 0; mi < 2; mi++)
#pragma unroll
        for (int ni = 0; ni < 8; ni++)
#pragma unroll
            for (int j = 0; j < 4; j++) c[mi][ni][j] = 0.f;

    loadA(0); loadB(0); cp_commit();
    loadA(1); loadB(1); cp_commit();
    loadA(2); loadB(2); cp_commit();

    for (int s = 0; s < nStages; s++) {
        if (s + 2 < nStages) cp_wait<2>();
        else if (s + 1 < nStages) cp_wait<1>();
        else cp_wait<0>();
        __syncthreads();
        uint32_t stg = sbase + (uint32_t)(s % 3) * STAGEB;
        uint32_t aHiB = stg, aLoB = stg + APLANE;
        uint32_t bHiB = stg + 2 * APLANE, bLoB = bHiB + BPLANE;
#pragma unroll
        for (int kc = 0; kc < 2; kc++) {
            uint32_t ah[2][4], al[2][4];
#pragma unroll
            for (int mi = 0; mi < 2; mi++) {
                int row = wm * 32 + mi * 16 + (lane & 15);
                uint32_t off = (uint32_t)row * 80 + kc * 32 + (lane >> 4) * 16;
                ldsm_x4(ah[mi][0], ah[mi][1], ah[mi][2], ah[mi][3], aHiB + off);
                ldsm_x4(al[mi][0], al[mi][1], al[mi][2], al[mi][3], aLoB + off);
            }
#pragma unroll
            for (int half = 0; half < 2; half++) {
                uint32_t bt[4][2], cl[4][2];
#pragma unroll
                for (int p = 0; p < 2; p++) {
                    int np = half * 2 + p;
                    int n = wn * 64 + np * 16 + ((lane >> 4) << 3) + (lane & 7);
                    uint32_t off = (uint32_t)n * 80 + kc * 32 + ((lane >> 3) & 1) * 16;
                    uint32_t h0, h1, h2, h3, l0, l1, l2, l3;
                    ldsm_x4(h0, h1, h2, h3, bHiB + off);
                    ldsm_x4(l0, l1, l2, l3, bLoB + off);
                    bt[2 * p][0] = h0; bt[2 * p][1] = h1;
                    bt[2 * p + 1][0] = h2; bt[2 * p + 1][1] = h3;
                    cl[2 * p][0] = l0; cl[2 * p][1] = l1;
                    cl[2 * p + 1][0] = l2; cl[2 * p + 1][1] = l3;
                }
#pragma unroll
                for (int t = 0; t < 4; t++)
#pragma unroll
                    for (int mi = 0; mi < 2; mi++)
                        mma_bf16(c[mi][half * 4 + t], ah[mi], bt[t]);
#pragma unroll
                for (int t = 0; t < 4; t++)
#pragma unroll
                    for (int mi = 0; mi < 2; mi++)
                        mma_bf16(c[mi][half * 4 + t], al[mi], bt[t]);
#pragma unroll
                for (int t = 0; t < 4; t++)
#pragma unroll
                    for (int mi = 0; mi < 2; mi++)
                        mma_bf16(c[mi][half * 4 + t], ah[mi], cl[t]);
            }
        }
        __syncthreads();
        if (s + 3 < nStages) { loadA(s + 3); loadB(s + 3); cp_commit(); }
    }

    // ---- epilogue: bias + rowscale + z write + fused column stats ----
    const float* bp = bias + ((mode == 0) ? plane * DD : 0);
    float* zbase = (mode == 0) ? (g_z + (size_t)plane * M * DD) : g_z;
    const int doScale = (mode == 0 && plane == 2);

    int r0A[2], r1A[2];
    float rs0A[2], rs1A[2];
#pragma unroll
    for (int mi = 0; mi < 2; mi++) {
        r0A[mi] = rowBase + wm * 32 + mi * 16 + (lane >> 2);
        r1A[mi] = r0A[mi] + 8;
        rs0A[mi] = (doScale && r0A[mi] < M) ? g_invdeg[r0A[mi]] : 1.f;
        rs1A[mi] = (doScale && r1A[mi] < M) ? g_invdeg[r1A[mi]] : 1.f;
    }
#pragma unroll
    for (int ni = 0; ni < 8; ni++) {
        int col = colBase + wn * 64 + ni * 8 + (lane & 3) * 2;
        float b0 = __ldg(bp + col), b1 = __ldg(bp + col + 1);
        float s0 = 0.f, s1 = 0.f, q0 = 0.f, q1 = 0.f;
#pragma unroll
        for (int mi = 0; mi < 2; mi++) {
            if (r0A[mi] < M) {
                float zx = fmaf(c[mi][ni][0], rs0A[mi], b0);
                float zy = fmaf(c[mi][ni][1], rs0A[mi], b1);
                *(float2*)(zbase + (size_t)r0A[mi] * DD + col) = make_float2(zx, zy);
                s0 += zx; q0 = fmaf(zx, zx, q0);
                s1 += zy; q1 = fmaf(zy, zy, q1);
            }
            if (r1A[mi] < M) {
                float zx = fmaf(c[mi][ni][2], rs1A[mi], b0);
                float zy = fmaf(c[mi][ni][3], rs1A[mi], b1);
                *(float2*)(zbase + (size_t)r1A[mi] * DD + col) = make_float2(zx, zy);
                s0 += zx; q0 = fmaf(zx, zx, q0);
                s1 += zy; q1 = fmaf(zy, zy, q1);
            }
        }
#pragma unroll
        for (int off = 4; off < 32; off <<= 1) {
            s0 += __shfl_xor_sync(0xffffffff, s0, off);
            s1 += __shfl_xor_sync(0xffffffff, s1, off);
            q0 += __shfl_xor_sync(0xffffffff, q0, off);
            q1 += __shfl_xor_sync(0xffffffff, q1, off);
        }
        if ((lane >> 2) == 0) {
            atomicAdd(&g_csum[plane * DD + col], s0);
            atomicAdd(&g_csum[plane * DD + col + 1], s1);
            atomicAdd(&g_csqr[plane * DD + col], q0);
            atomicAdd(&g_csqr[plane * DD + col + 1], q1);
        }
    }
}

__global__ void k_finalize(const float* __restrict__ gam, const float* __restrict__ bet,
                           int M, int P) {
    int i = blockIdx.x * blockDim.x + threadIdx.x;
    if (i < P * DD) {
        float inv = 1.0f / (float)M;
        float mu = g_csum[i] * inv;
        float var = g_csqr[i] * inv - mu * mu;
        float sc = rsqrtf(var + 1e-5f) * gam[i];
        g_scale[i] = sc;
        g_shift[i] = bet[i] - mu * sc;
    }
}

// ------- weighted relu combine over k (+ fused bf16 hi/lo split of result) -------
__global__ void k_combine(const float* __restrict__ w, float* __restrict__ out,
                          int M, int acc, int slot, int doSplit) {
    int idx = blockIdx.x * blockDim.x + threadIdx.x;
    int total = M * NV4;
    if (idx >= total) return;
    int dc = (idx % NV4) * 4;
    float4 r = acc ? ((const float4*)out)[idx] : make_float4(0.f, 0.f, 0.f, 0.f);
#pragma unroll
    for (int k = 0; k < 4; k++) {
        float wk = __ldg(w + k);
        float4 v = __ldg((const float4*)g_z + (size_t)k * M * NV4 + idx);
        float4 sc = *(const float4*)&g_scale[k * DD + dc];
        float4 sh = *(const float4*)&g_shift[k * DD + dc];
        float e;
        e = fmaxf(fmaf(v.x, sc.x, sh.x), 0.f); r.x = fmaf(wk, e, r.x);
        e = fmaxf(fmaf(v.y, sc.y, sh.y), 0.f); r.y = fmaf(wk, e, r.y);
        e = fmaxf(fmaf(v.z, sc.z, sh.z), 0.f); r.z = fmaf(wk, e, r.z);
        e = fmaxf(fmaf(v.w, sc.w, sh.w), 0.f); r.w = fmaf(wk, e, r.w);
    }
    ((float4*)out)[idx] = r;
    if (doSplit) {
        uint32_t* sh = (uint32_t*)(g_slh + (size_t)slot * NN * DD);
        uint32_t* sl = (uint32_t*)(g_sll + (size_t)slot * NN * DD);
        uint32_t h, l;
        split2(r.x, r.y, h, l); sh[idx * 2] = h; sl[idx * 2] = l;
        split2(r.z, r.w, h, l); sh[idx * 2 + 1] = h; sl[idx * 2 + 1] = l;
    }
}

// ---------------- final residual + BN + relu ----------------
__global__ void k_final(const float* __restrict__ h, float* __restrict__ out, int M) {
    int idx = blockIdx.x * blockDim.x + threadIdx.x;
    int total = M * NV4;
    if (idx >= total) return;
    int dc = (idx % NV4) * 4;
    float4 v = ((const float4*)g_z)[idx];
    float4 sc = *(const float4*)&g_scale[dc];
    float4 sh = *(const float4*)&g_shift[dc];
    float4 hv = ((const float4*)h)[idx];
    float4 o;
    o.x = hv.x + fmaxf(fmaf(v.x, sc.x, sh.x), 0.f);
    o.y = hv.y + fmaxf(fmaf(v.y, sc.y, sh.y), 0.f);
    o.z = hv.z + fmaxf(fmaf(v.z, sc.z, sh.z), 0.f);
    o.w = hv.w + fmaxf(fmaf(v.w, sc.w, sh.w), 0.f);
    ((float4*)out)[idx] = o;
}

// ---------------- host orchestration ----------------
static void run_mixed(int wslab, const float* b4, const float* g4, const float* be4,
                      const float* w4, int inSlot, float* outp, int acc,
                      int outSlot, int doSplit, int M, void* sump, void* sqrp) {
    cudaMemsetAsync(sump, 0, 4 * DD * sizeof(float));
    cudaMemsetAsync(sqrp, 0, 4 * DD * sizeof(float));
    k_gemm_mma<<<dim3((M + 127) / 128, 2, 4), 512, SMEM_GEMM>>>(
        b4, M, 0, inSlot, (size_t)wslab * SLAB);
    k_finalize<<<8, 256>>>(g4, be4, M, 4);
    k_combine<<<(M * NV4 + 255) / 256, 256>>>(w4, outp, M, acc, outSlot, doSplit);
}

extern "C" void kernel_launch(void* const* d_in, const int* in_sizes, int n_in,
                              void* d_out, int out_size) {
    const float* h    = (const float*)d_in[0];
    const int*   src  = (const int*)d_in[1];
    const int*   dst  = (const int*)d_in[2];
    const float* wf   = (const float*)d_in[3];
    const float* wm   = (const float*)d_in[4];
    const float* wl   = (const float*)d_in[5];
    const float* pfW  = (const float*)d_in[6];
    const float* pfb  = (const float*)d_in[7];
    const float* pfg  = (const float*)d_in[8];
    const float* pfB  = (const float*)d_in[9];
    const float* pmW  = (const float*)d_in[10];
    const float* pmb  = (const float*)d_in[11];
    const float* pmg  = (const float*)d_in[12];
    const float* pmB  = (const float*)d_in[13];
    const float* plW  = (const float*)d_in[14];
    const float* plb  = (const float*)d_in[15];
    const float* plg  = (const float*)d_in[16];
    const float* plB  = (const float*)d_in[17];
    const float* catW = (const float*)d_in[18];
    const float* catb = (const float*)d_in[19];
    const float* bng  = (const float*)d_in[20];
    const float* bnb  = (const float*)d_in[21];

    int M = in_sizes[0] / DD;
    int E = in_sizes[1];
    float* out = (float*)d_out;

    cudaFuncSetAttribute(k_gemm_mma, cudaFuncAttributeMaxDynamicSharedMemorySize, SMEM_GEMM);

    void *s1, *s2, *m1, *m2, *l1, *l2, *degp, *sump, *sqrp;
    cudaGetSymbolAddress(&s1, g_s1);
    cudaGetSymbolAddress(&s2, g_s2);
    cudaGetSymbolAddress(&m1, g_m1);
    cudaGetSymbolAddress(&m2, g_m2);
    cudaGetSymbolAddress(&l1, g_l1);
    cudaGetSymbolAddress(&l2, g_l2);
    cudaGetSymbolAddress(&degp, g_deg);
    cudaGetSymbolAddress(&sump, g_csum);
    cudaGetSymbolAddress(&sqrp, g_csqr);

    const size_t slabB = 4 * DD;
    const int nsp = (M * NV4 + 255) / 256;

    // ---- all weight prep up front (4 launches) ----
    k_prep<<<dim3(16, 16, 12), 256>>>(pfW, 0, 512, 512);
    k_prep<<<dim3(16, 16, 8), 256>>>(pmW, 12 * SLAB, 512, 512);
    k_prep<<<dim3(16, 16, 20), 256>>>(plW, 20 * SLAB, 512, 512);
    k_prep<<<dim3(64, 16, 1), 256>>>(catW, 40 * SLAB, 2048, 512);

    // CSR build (shared by all aggregations this launch)
    cudaMemsetAsync(degp, 0, M * sizeof(int));
    k_count<<<(E + 255) / 256, 256>>>(dst, E);
    k_scan<<<1, 1024>>>(M);
    k_scatter<<<(E + 255) / 256, 256>>>(src, dst, E);

    // first block: s1 = mixed(wf0, h); s2 = mixed(wf1, h) + mixed(wf2, s1)
    k_aggregate<<<M, 128>>>(h, M);
    k_split<<<nsp, 256>>>(h, 0, M);
    run_mixed(0, pfb + 0 * slabB, pfg + 0 * slabB, pfB + 0 * slabB, wf + 0,
              0, (float*)s1, 0, 1, 1, M, sump, sqrp);
    run_mixed(4, pfb + 1 * slabB, pfg + 1 * slabB, pfB + 1 * slabB, wf + 4,
              0, (float*)s2, 0, 2, 0, M, sump, sqrp);
    k_aggregate<<<M, 128>>>((const float*)s1, M);
    run_mixed(8, pfb + 2 * slabB, pfg + 2 * slabB, pfB + 2 * slabB, wf + 8,
              1, (float*)s2, 1, 2, 1, M, sump, sqrp);
    // middle (agg(s1) still in slots 7/8): m1 = mixed(wm0, s1)
    run_mixed(12, pmb + 0 * slabB, pmg + 0 * slabB, pmB + 0 * slabB, wm + 0,
              1, (float*)m1, 0, 3, 1, M, sump, sqrp);
    k_aggregate<<<M, 128>>>((const float*)s2, M);
    run_mixed(16, pmb + 1 * slabB, pmg + 1 * slabB, pmB + 1 * slabB, wm + 4,
              2, (float*)m2, 0, 4, 1, M, sump, sqrp);
    // last block: l1 = mixed(wl0,m1)+mixed(wl1,m2); l2 = mixed(wl2,m1)+mixed(wl3,m2)+mixed(wl4,l1)
    k_aggregate<<<M, 128>>>((const float*)m1, M);
    run_mixed(20, plb + 0 * slabB, plg + 0 * slabB, plB + 0 * slabB, wl + 0,
              3, (float*)l1, 0, 5, 0, M, sump, sqrp);
    run_mixed(28, plb + 2 * slabB, plg + 2 * slabB, plB + 2 * slabB, wl + 8,
              3, (float*)l2, 0, 6, 0, M, sump, sqrp);
    k_aggregate<<<M, 128>>>((const float*)m2, M);
    run_mixed(24, plb + 1 * slabB, plg + 1 * slabB, plB + 1 * slabB, wl + 4,
              4, (float*)l1, 1, 5, 1, M, sump, sqrp);
    run_mixed(32, plb + 3 * slabB, plg + 3 * slabB, plB + 3 * slabB, wl + 12,
              4, (float*)l2, 1, 6, 0, M, sump, sqrp);
    k_aggregate<<<M, 128>>>((const float*)l1, M);
    run_mixed(36, plb + 4 * slabB, plg + 4 * slabB, plB + 4 * slabB, wl + 16,
              5, (float*)l2, 1, 6, 1, M, sump, sqrp);

    // cat GEMM + batchnorm + relu + residual
    cudaMemsetAsync(sump, 0, 4 * DD * sizeof(float));
    cudaMemsetAsync(sqrp, 0, 4 * DD * sizeof(float));
    k_gemm_mma<<<dim3((M + 127) / 128, 2, 1), 512, SMEM_GEMM>>>(
        catb, M, 1, 0, (size_t)40 * SLAB);
    k_finalize<<<8, 256>>>(bng, bnb, M, 1);
    k_final<<<nsp, 256>>>(h, out, M);
}

// round 12
// speedup vs baseline: 1.1296x; 1.1183x over previous
#include <cuda_runtime.h>
#include <cuda_bf16.h>
#include <cstdint>

#define NN 50000
#define EE 800000
#define DD 512
#define NV4 (DD/4)
#define SLAB ((size_t)512 * 512)

// ---------------- static scratch (no allocations allowed) ----------------
__device__ float g_s1[(size_t)NN * DD];
__device__ float g_s2[(size_t)NN * DD];
__device__ float g_m1[(size_t)NN * DD];
__device__ float g_m2[(size_t)NN * DD];
__device__ float g_l1[(size_t)NN * DD];
__device__ float g_l2[(size_t)NN * DD];
__device__ float g_z[(size_t)4 * NN * DD];  // z planes (plane 0 reused for cat out)
// slots: 0=h 1=s1 2=s2 3=m1 4=m2 5=l1 6=l2 7=aggsum 8=aggmax
__device__ __nv_bfloat16 g_slh[(size_t)9 * NN * DD];
__device__ __nv_bfloat16 g_sll[(size_t)9 * NN * DD];
__device__ __nv_bfloat16 g_bh[44 * SLAB];   // B transposed hi (40 mixed slabs + cat)
__device__ __nv_bfloat16 g_bl[44 * SLAB];   // B transposed lo
__device__ int   g_deg[NN];
__device__ int   g_rowp[NN + 1];
__device__ int   g_cur[NN];
__device__ int   g_csrc[EE];
__device__ float g_invdeg[NN];
__device__ float g_csum[4 * DD];
__device__ float g_csqr[4 * DD];
__device__ float g_scale[4 * DD];
__device__ float g_shift[4 * DD];

// ---------------- PTX helpers (sm_80-generic only) ----------------
__device__ __forceinline__ uint32_t smem_u32(const void* p) {
    uint32_t a;
    asm("{ .reg .u64 t; cvta.to.shared.u64 t, %1; cvt.u32.u64 %0, t; }" : "=r"(a) : "l"(p));
    return a;
}
__device__ __forceinline__ void cp_async16(uint32_t saddr, const void* gaddr, int sz) {
    asm volatile("cp.async.cg.shared.global [%0], [%1], 16, %2;"
                 :: "r"(saddr), "l"(gaddr), "r"(sz));
}
__device__ __forceinline__ void cp_commit() {
    asm volatile("cp.async.commit_group;");
}
template <int N>
__device__ __forceinline__ void cp_wait() {
    asm volatile("cp.async.wait_group %0;" :: "n"(N));
}
__device__ __forceinline__ void ldsm_x4(uint32_t& r0, uint32_t& r1, uint32_t& r2,
                                        uint32_t& r3, uint32_t addr) {
    asm volatile("ldmatrix.sync.aligned.m8n8.x4.shared.b16 {%0,%1,%2,%3}, [%4];"
                 : "=r"(r0), "=r"(r1), "=r"(r2), "=r"(r3) : "r"(addr));
}
__device__ __forceinline__ void mma_bf16(float* c, const uint32_t* a, const uint32_t* b) {
    asm volatile(
        "mma.sync.aligned.m16n8k16.row.col.f32.bf16.bf16.f32 "
        "{%0,%1,%2,%3}, {%4,%5,%6,%7}, {%8,%9}, {%0,%1,%2,%3};"
        : "+f"(c[0]), "+f"(c[1]), "+f"(c[2]), "+f"(c[3])
        : "r"(a[0]), "r"(a[1]), "r"(a[2]), "r"(a[3]), "r"(b[0]), "r"(b[1]));
}

__device__ __forceinline__ void split2(float x, float y, uint32_t& hi, uint32_t& lo) {
    __nv_bfloat162 h = __floats2bfloat162_rn(x, y);
    float rx = x - __bfloat162float(__low2bfloat16(h));
    float ry = y - __bfloat162float(__high2bfloat16(h));
    __nv_bfloat162 l = __floats2bfloat162_rn(rx, ry);
    hi = *(uint32_t*)&h;
    lo = *(uint32_t*)&l;
}

// ---------------- CSR build ----------------
__global__ void k_count(const int* __restrict__ dst, int E) {
    int e = blockIdx.x * blockDim.x + threadIdx.x;
    if (e < E) atomicAdd(&g_deg[dst[e]], 1);
}

__global__ void k_scan(int M) {
    __shared__ int sh[1024];
    __shared__ int running;
    if (threadIdx.x == 0) running = 0;
    __syncthreads();
    for (int base = 0; base < M; base += 1024) {
        int i = base + threadIdx.x;
        int v = (i < M) ? g_deg[i] : 0;
        sh[threadIdx.x] = v;
        __syncthreads();
        for (int off = 1; off < 1024; off <<= 1) {
            int t = 0;
            if ((int)threadIdx.x >= off) t = sh[threadIdx.x - off];
            __syncthreads();
            sh[threadIdx.x] += t;
            __syncthreads();
        }
        int incl = sh[threadIdx.x];
        int excl = running + incl - v;
        if (i < M) {
            g_rowp[i] = excl;
            g_cur[i] = excl;
            g_invdeg[i] = 1.0f / (float)(v > 1 ? v : 1);
        }
        __syncthreads();
        if (threadIdx.x == 0) running += sh[1023];
        __syncthreads();
    }
    if (threadIdx.x == 0) g_rowp[M] = running;
}

__global__ void k_scatter(const int* __restrict__ src, const int* __restrict__ dst, int E) {
    int e = blockIdx.x * blockDim.x + threadIdx.x;
    if (e < E) {
        int d = dst[e];
        int p = atomicAdd(&g_cur[d], 1);
        g_csrc[p] = src[e];
    }
}

// ------- aggregation: one block per node; bf16 hi/lo into slots 7 (sum), 8 (max) -------
__global__ void k_aggregate(const float* __restrict__ X, int M) {
    int nid = blockIdx.x;
    int t = threadIdx.x;
    int beg = g_rowp[nid], end = g_rowp[nid + 1];
    float4 s = make_float4(0.f, 0.f, 0.f, 0.f);
    float4 m = make_float4(-3.4e38f, -3.4e38f, -3.4e38f, -3.4e38f);
    const float4* Xb = (const float4*)X;
    for (int e = beg; e < end; e++) {
        int r = __ldg(&g_csrc[e]);
        float4 v = __ldg(Xb + (size_t)r * NV4 + t);
        s.x += v.x; s.y += v.y; s.z += v.z; s.w += v.w;
        m.x = fmaxf(m.x, v.x); m.y = fmaxf(m.y, v.y);
        m.z = fmaxf(m.z, v.z); m.w = fmaxf(m.w, v.w);
    }
    if (beg == end) m = make_float4(0.f, 0.f, 0.f, 0.f);
    size_t base = (size_t)nid * 256 + t * 2;  // in bf16x2 units
    uint32_t* sh1 = (uint32_t*)(g_slh + (size_t)7 * NN * DD);
    uint32_t* sl1 = (uint32_t*)(g_sll + (size_t)7 * NN * DD);
    uint32_t* sh2 = (uint32_t*)(g_slh + (size_t)8 * NN * DD);
    uint32_t* sl2 = (uint32_t*)(g_sll + (size_t)8 * NN * DD);
    uint32_t h, l;
    split2(s.x, s.y, h, l); sh1[base] = h; sl1[base] = l;
    split2(s.z, s.w, h, l); sh1[base + 1] = h; sl1[base + 1] = l;
    split2(m.x, m.y, h, l); sh2[base] = h; sl2[base] = l;
    split2(m.z, m.w, h, l); sh2[base + 1] = h; sl2[base + 1] = l;
}

// ---------------- split fp32 state into bf16 hi/lo slot ----------------
__global__ void k_split(const float* __restrict__ X, int slot, int M) {
    int idx = blockIdx.x * blockDim.x + threadIdx.x;
    int total = M * NV4;
    if (idx >= total) return;
    float4 v = ((const float4*)X)[idx];
    uint32_t* sh = (uint32_t*)(g_slh + (size_t)slot * NN * DD);
    uint32_t* sl = (uint32_t*)(g_sll + (size_t)slot * NN * DD);
    uint32_t h, l;
    split2(v.x, v.y, h, l); sh[idx * 2] = h; sl[idx * 2] = l;
    split2(v.z, v.w, h, l); sh[idx * 2 + 1] = h; sl[idx * 2 + 1] = l;
}

// ------ weight prep: transpose [K][N]->[N][K] + bf16 hi/lo split ------
__global__ void k_prep(const float* __restrict__ W, size_t dofs, int K, int N) {
    __shared__ float t[32][33];
    const float* Wp = W + (size_t)blockIdx.z * K * N;
    __nv_bfloat16* oh = g_bh + dofs + (size_t)blockIdx.z * K * N;
    __nv_bfloat16* ol = g_bl + dofs + (size_t)blockIdx.z * K * N;
    int k0 = blockIdx.x * 32;
    int n0 = blockIdx.y * 32;
    int tx = threadIdx.x & 31, ty = threadIdx.x >> 5;
    for (int r = ty; r < 32; r += 8)
        t[r][tx] = __ldg(Wp + (size_t)(k0 + r) * N + n0 + tx);
    __syncthreads();
    for (int r = ty; r < 32; r += 8) {
        float w = t[tx][r];
        __nv_bfloat16 hb = __float2bfloat16_rn(w);
        float lof = w - __bfloat162float(hb);
        size_t o = (size_t)(n0 + r) * K + k0 + tx;
        oh[o] = hb;
        ol[o] = __float2bfloat16_rn(lof);
    }
}

// ---------------- bf16x3 mma.sync GEMM (+ fused BN stats in epilogue) ----------------
// CTA 128x128 tile, 256 thr (8 warps: 4m x 2n), warp 32x64, BK=32, 2-stage, 2 CTAs/SM.
// grid: x = plane*4 + colTile (mode0, 16) / colTile (mode1, 4); y = row tile.
// mode 0: z[plane] = A_slot @ B[bofs + plane*SLAB] (K=512)
//         A slot: plane0 -> aslot, planes 1,2 -> 7 (sum), plane3 -> 8 (max)
// mode 1: z[0] = [slot3|slot4|slot5|slot6] @ B[bofs] (K=2048)
#define APLANE 10240                       // 128 rows * 80B
#define BPLANE 10240                       // 128 rows * 80B
#define STAGEB (2 * APLANE + 2 * BPLANE)   // 40960
#define SMEM_GEMM (2 * STAGEB)             // 81920

__global__ void __launch_bounds__(256, 2)
k_gemm_mma(const float* __restrict__ bias, int M, int mode, int aslot, size_t bofs) {
    extern __shared__ char smem[];
    uint32_t sbase = smem_u32(smem);
    const int tid = threadIdx.x;
    const int wid = tid >> 5, lane = tid & 31;
    const int wm = wid & 3, wn = wid >> 2;
    const int plane = (mode == 0) ? (blockIdx.x >> 2) : 0;
    const int colBase = ((mode == 0) ? (blockIdx.x & 3) : blockIdx.x) * 128;
    const int rowBase = blockIdx.y * 128;

    const int K = (mode == 0) ? 512 : 2048;
    const int nStages = K / 32;
    const int bK = K;
    const size_t bOff = bofs + ((mode == 0) ? (size_t)plane * SLAB : 0);

    auto loadA = [&](int s) {
        int slot, kin;
        if (mode == 0) {
            slot = (plane == 0) ? aslot : ((plane == 3) ? 8 : 7);
            kin = s * 32;
        } else {
            slot = 3 + (s >> 4);
            kin = (s & 15) * 32;
        }
        const __nv_bfloat16* aH = g_slh + (size_t)slot * NN * DD;
        const __nv_bfloat16* aL = g_sll + (size_t)slot * NN * DD;
        uint32_t stg = sbase + (uint32_t)(s & 1) * STAGEB;
#pragma unroll
        for (int i = 0; i < 4; i++) {
            int idx = tid + 256 * i;
            int pl = idx >> 9, r = (idx >> 2) & 127, ch = idx & 3;
            int grow = rowBase + r;
            int gr = (grow < M) ? grow : (M - 1);
            const __nv_bfloat16* gp = (pl ? aL : aH) + (size_t)gr * 512 + kin + ch * 8;
            uint32_t dst = stg + pl * APLANE + r * 80 + ch * 16;
            cp_async16(dst, gp, (grow < M) ? 16 : 0);
        }
    };
    auto loadB = [&](int s) {
        int kin = s * 32;
        uint32_t stg = sbase + (uint32_t)(s & 1) * STAGEB + 2 * APLANE;
#pragma unroll
        for (int i = 0; i < 4; i++) {
            int idx = tid + 256 * i;
            int pl = idx >> 9, r = (idx >> 2) & 127, ch = idx & 3;
            const __nv_bfloat16* gp =
                (pl ? g_bl : g_bh) + bOff + (size_t)(colBase + r) * bK + kin + ch * 8;
            uint32_t dst = stg + pl * BPLANE + r * 80 + ch * 16;
            cp_async16(dst, gp, 16);
        }
    };

    float c[2][8][4];
#pragma unroll
    for (int mi = 0; mi < 2; mi++)
#pragma unroll
        for (int ni = 0; ni < 8; ni++)
#pragma unroll
            for (int j = 0; j < 4; j++) c[mi][ni][j] = 0.f;

    loadA(0); loadB(0); cp_commit();
    loadA(1); loadB(1); cp_commit();

    for (int s = 0; s < nStages; s++) {
        if (s + 1 < nStages) cp_wait<1>(); else cp_wait<0>();
        __syncthreads();
        uint32_t stg = sbase + (uint32_t)(s & 1) * STAGEB;
        uint32_t aHiB = stg, aLoB = stg + APLANE;
        uint32_t bHiB = stg + 2 * APLANE, bLoB = bHiB + BPLANE;
#pragma unroll
        for (int kc = 0; kc < 2; kc++) {
            uint32_t ah[2][4], al[2][4];
#pragma unroll
            for (int mi = 0; mi < 2; mi++) {
                int row = wm * 32 + mi * 16 + (lane & 15);
                uint32_t off = (uint32_t)row * 80 + kc * 32 + (lane >> 4) * 16;
                ldsm_x4(ah[mi][0], ah[mi][1], ah[mi][2], ah[mi][3], aHiB + off);
                ldsm_x4(al[mi][0], al[mi][1], al[mi][2], al[mi][3], aLoB + off);
            }
#pragma unroll
            for (int half = 0; half < 2; half++) {
                uint32_t bt[4][2], cl[4][2];
#pragma unroll
                for (int p = 0; p < 2; p++) {
                    int np = half * 2 + p;
                    int n = wn * 64 + np * 16 + ((lane >> 4) << 3) + (lane & 7);
                    uint32_t off = (uint32_t)n * 80 + kc * 32 + ((lane >> 3) & 1) * 16;
                    uint32_t h0, h1, h2, h3, l0, l1, l2, l3;
                    ldsm_x4(h0, h1, h2, h3, bHiB + off);
                    ldsm_x4(l0, l1, l2, l3, bLoB + off);
                    bt[2 * p][0] = h0; bt[2 * p][1] = h1;
                    bt[2 * p + 1][0] = h2; bt[2 * p + 1][1] = h3;
                    cl[2 * p][0] = l0; cl[2 * p][1] = l1;
                    cl[2 * p + 1][0] = l2; cl[2 * p + 1][1] = l3;
                }
#pragma unroll
                for (int t = 0; t < 4; t++)
#pragma unroll
                    for (int mi = 0; mi < 2; mi++)
                        mma_bf16(c[mi][half * 4 + t], ah[mi], bt[t]);
#pragma unroll
                for (int t = 0; t < 4; t++)
#pragma unroll
                    for (int mi = 0; mi < 2; mi++)
                        mma_bf16(c[mi][half * 4 + t], al[mi], bt[t]);
#pragma unroll
                for (int t = 0; t < 4; t++)
#pragma unroll
                    for (int mi = 0; mi < 2; mi++)
                        mma_bf16(c[mi][half * 4 + t], ah[mi], cl[t]);
            }
        }
        __syncthreads();
        if (s + 2 < nStages) { loadA(s + 2); loadB(s + 2); cp_commit(); }
    }

    // ---- epilogue: bias + rowscale + z write + fused column stats ----
    const float* bp = bias + ((mode == 0) ? plane * DD : 0);
    float* zbase = (mode == 0) ? (g_z + (size_t)plane * M * DD) : g_z;
    const int doScale = (mode == 0 && plane == 2);

    int r0A[2], r1A[2];
    float rs0A[2], rs1A[2];
#pragma unroll
    for (int mi = 0; mi < 2; mi++) {
        r0A[mi] = rowBase + wm * 32 + mi * 16 + (lane >> 2);
        r1A[mi] = r0A[mi] + 8;
        rs0A[mi] = (doScale && r0A[mi] < M) ? g_invdeg[r0A[mi]] : 1.f;
        rs1A[mi] = (doScale && r1A[mi] < M) ? g_invdeg[r1A[mi]] : 1.f;
    }
#pragma unroll
    for (int ni = 0; ni < 8; ni++) {
        int col = colBase + wn * 64 + ni * 8 + (lane & 3) * 2;
        float b0 = __ldg(bp + col), b1 = __ldg(bp + col + 1);
        float s0 = 0.f, s1 = 0.f, q0 = 0.f, q1 = 0.f;
#pragma unroll
        for (int mi = 0; mi < 2; mi++) {
            if (r0A[mi] < M) {
                float zx = fmaf(c[mi][ni][0], rs0A[mi], b0);
                float zy = fmaf(c[mi][ni][1], rs0A[mi], b1);
                *(float2*)(zbase + (size_t)r0A[mi] * DD + col) = make_float2(zx, zy);
                s0 += zx; q0 = fmaf(zx, zx, q0);
                s1 += zy; q1 = fmaf(zy, zy, q1);
            }
            if (r1A[mi] < M) {
                float zx = fmaf(c[mi][ni][2], rs1A[mi], b0);
                float zy = fmaf(c[mi][ni][3], rs1A[mi], b1);
                *(float2*)(zbase + (size_t)r1A[mi] * DD + col) = make_float2(zx, zy);
                s0 += zx; q0 = fmaf(zx, zx, q0);
                s1 += zy; q1 = fmaf(zy, zy, q1);
            }
        }
#pragma unroll
        for (int off = 4; off < 32; off <<= 1) {
            s0 += __shfl_xor_sync(0xffffffff, s0, off);
            s1 += __shfl_xor_sync(0xffffffff, s1, off);
            q0 += __shfl_xor_sync(0xffffffff, q0, off);
            q1 += __shfl_xor_sync(0xffffffff, q1, off);
        }
        if ((lane >> 2) == 0) {
            atomicAdd(&g_csum[plane * DD + col], s0);
            atomicAdd(&g_csum[plane * DD + col + 1], s1);
            atomicAdd(&g_csqr[plane * DD + col], q0);
            atomicAdd(&g_csqr[plane * DD + col + 1], q1);
        }
    }
}

__global__ void k_finalize(const float* __restrict__ gam, const float* __restrict__ bet,
                           int M, int P) {
    int i = blockIdx.x * blockDim.x + threadIdx.x;
    if (i < P * DD) {
        float inv = 1.0f / (float)M;
        float mu = g_csum[i] * inv;
        float var = g_csqr[i] * inv - mu * mu;
        float sc = rsqrtf(var + 1e-5f) * gam[i];
        g_scale[i] = sc;
        g_shift[i] = bet[i] - mu * sc;
    }
}

// ------- weighted relu combine over k (+ fused bf16 hi/lo split of result) -------
__global__ void k_combine(const float* __restrict__ w, float* __restrict__ out,
                          int M, int acc, int slot, int doSplit) {
    int idx = blockIdx.x * blockDim.x + threadIdx.x;
    int total = M * NV4;
    if (idx >= total) return;
    int dc = (idx % NV4) * 4;
    float4 r = acc ? ((const float4*)out)[idx] : make_float4(0.f, 0.f, 0.f, 0.f);
#pragma unroll
    for (int k = 0; k < 4; k++) {
        float wk = __ldg(w + k);
        float4 v = __ldg((const float4*)g_z + (size_t)k * M * NV4 + idx);
        float4 sc = *(const float4*)&g_scale[k * DD + dc];
        float4 sh = *(const float4*)&g_shift[k * DD + dc];
        float e;
        e = fmaxf(fmaf(v.x, sc.x, sh.x), 0.f); r.x = fmaf(wk, e, r.x);
        e = fmaxf(fmaf(v.y, sc.y, sh.y), 0.f); r.y = fmaf(wk, e, r.y);
        e = fmaxf(fmaf(v.z, sc.z, sh.z), 0.f); r.z = fmaf(wk, e, r.z);
        e = fmaxf(fmaf(v.w, sc.w, sh.w), 0.f); r.w = fmaf(wk, e, r.w);
    }
    ((float4*)out)[idx] = r;
    if (doSplit) {
        uint32_t* sh = (uint32_t*)(g_slh + (size_t)slot * NN * DD);
        uint32_t* sl = (uint32_t*)(g_sll + (size_t)slot * NN * DD);
        uint32_t h, l;
        split2(r.x, r.y, h, l); sh[idx * 2] = h; sl[idx * 2] = l;
        split2(r.z, r.w, h, l); sh[idx * 2 + 1] = h; sl[idx * 2 + 1] = l;
    }
}

// ---------------- final residual + BN + relu ----------------
__global__ void k_final(const float* __restrict__ h, float* __restrict__ out, int M) {
    int idx = blockIdx.x * blockDim.x + threadIdx.x;
    int total = M * NV4;
    if (idx >= total) return;
    int dc = (idx % NV4) * 4;
    float4 v = ((const float4*)g_z)[idx];
    float4 sc = *(const float4*)&g_scale[dc];
    float4 sh = *(const float4*)&g_shift[dc];
    float4 hv = ((const float4*)h)[idx];
    float4 o;
    o.x = hv.x + fmaxf(fmaf(v.x, sc.x, sh.x), 0.f);
    o.y = hv.y + fmaxf(fmaf(v.y, sc.y, sh.y), 0.f);
    o.z = hv.z + fmaxf(fmaf(v.z, sc.z, sh.z), 0.f);
    o.w = hv.w + fmaxf(fmaf(v.w, sc.w, sh.w), 0.f);
    ((float4*)out)[idx] = o;
}

// ---------------- host orchestration ----------------
static void run_mixed(int wslab, const float* b4, const float* g4, const float* be4,
                      const float* w4, int inSlot, float* outp, int acc,
                      int outSlot, int doSplit, int M, void* sump, void* sqrp) {
    cudaMemsetAsync(sump, 0, 4 * DD * sizeof(float));
    cudaMemsetAsync(sqrp, 0, 4 * DD * sizeof(float));
    k_gemm_mma<<<dim3(16, (M + 127) / 128, 1), 256, SMEM_GEMM>>>(
        b4, M, 0, inSlot, (size_t)wslab * SLAB);
    k_finalize<<<8, 256>>>(g4, be4, M, 4);
    k_combine<<<(M * NV4 + 255) / 256, 256>>>(w4, outp, M, acc, outSlot, doSplit);
}

extern "C" void kernel_launch(void* const* d_in, const int* in_sizes, int n_in,
                              void* d_out, int out_size) {
    const float* h    = (const float*)d_in[0];
    const int*   src  = (const int*)d_in[1];
    const int*   dst  = (const int*)d_in[2];
    const float* wf   = (const float*)d_in[3];
    const float* wm   = (const float*)d_in[4];
    const float* wl   = (const float*)d_in[5];
    const float* pfW  = (const float*)d_in[6];
    const float* pfb  = (const float*)d_in[7];
    const float* pfg  = (const float*)d_in[8];
    const float* pfB  = (const float*)d_in[9];
    const float* pmW  = (const float*)d_in[10];
    const float* pmb  = (const float*)d_in[11];
    const float* pmg  = (const float*)d_in[12];
    const float* pmB  = (const float*)d_in[13];
    const float* plW  = (const float*)d_in[14];
    const float* plb  = (const float*)d_in[15];
    const float* plg  = (const float*)d_in[16];
    const float* plB  = (const float*)d_in[17];
    const float* catW = (const float*)d_in[18];
    const float* catb = (const float*)d_in[19];
    const float* bng  = (const float*)d_in[20];
    const float* bnb  = (const float*)d_in[21];

    int M = in_sizes[0] / DD;
    int E = in_sizes[1];
    float* out = (float*)d_out;

    cudaFuncSetAttribute(k_gemm_mma, cudaFuncAttributeMaxDynamicSharedMemorySize, SMEM_GEMM);

    void *s1, *s2, *m1, *m2, *l1, *l2, *degp, *sump, *sqrp;
    cudaGetSymbolAddress(&s1, g_s1);
    cudaGetSymbolAddress(&s2, g_s2);
    cudaGetSymbolAddress(&m1, g_m1);
    cudaGetSymbolAddress(&m2, g_m2);
    cudaGetSymbolAddress(&l1, g_l1);
    cudaGetSymbolAddress(&l2, g_l2);
    cudaGetSymbolAddress(&degp, g_deg);
    cudaGetSymbolAddress(&sump, g_csum);
    cudaGetSymbolAddress(&sqrp, g_csqr);

    const size_t slabB = 4 * DD;
    const int nsp = (M * NV4 + 255) / 256;

    // ---- all weight prep up front (4 launches) ----
    k_prep<<<dim3(16, 16, 12), 256>>>(pfW, 0, 512, 512);
    k_prep<<<dim3(16, 16, 8), 256>>>(pmW, 12 * SLAB, 512, 512);
    k_prep<<<dim3(16, 16, 20), 256>>>(plW, 20 * SLAB, 512, 512);
    k_prep<<<dim3(64, 16, 1), 256>>>(catW, 40 * SLAB, 2048, 512);

    // CSR build (shared by all aggregations this launch)
    cudaMemsetAsync(degp, 0, M * sizeof(int));
    k_count<<<(E + 255) / 256, 256>>>(dst, E);
    k_scan<<<1, 1024>>>(M);
    k_scatter<<<(E + 255) / 256, 256>>>(src, dst, E);

    // first block: s1 = mixed(wf0, h); s2 = mixed(wf1, h) + mixed(wf2, s1)
    k_aggregate<<<M, 128>>>(h, M);
    k_split<<<nsp, 256>>>(h, 0, M);
    run_mixed(0, pfb + 0 * slabB, pfg + 0 * slabB, pfB + 0 * slabB, wf + 0,
              0, (float*)s1, 0, 1, 1, M, sump, sqrp);
    run_mixed(4, pfb + 1 * slabB, pfg + 1 * slabB, pfB + 1 * slabB, wf + 4,
              0, (float*)s2, 0, 2, 0, M, sump, sqrp);
    k_aggregate<<<M, 128>>>((const float*)s1, M);
    run_mixed(8, pfb + 2 * slabB, pfg + 2 * slabB, pfB + 2 * slabB, wf + 8,
              1, (float*)s2, 1, 2, 1, M, sump, sqrp);
    // middle (agg(s1) still in slots 7/8): m1 = mixed(wm0, s1)
    run_mixed(12, pmb + 0 * slabB, pmg + 0 * slabB, pmB + 0 * slabB, wm + 0,
              1, (float*)m1, 0, 3, 1, M, sump, sqrp);
    k_aggregate<<<M, 128>>>((const float*)s2, M);
    run_mixed(16, pmb + 1 * slabB, pmg + 1 * slabB, pmB + 1 * slabB, wm + 4,
              2, (float*)m2, 0, 4, 1, M, sump, sqrp);
    // last block: l1 = mixed(wl0,m1)+mixed(wl1,m2); l2 = mixed(wl2,m1)+mixed(wl3,m2)+mixed(wl4,l1)
    k_aggregate<<<M, 128>>>((const float*)m1, M);
    run_mixed(20, plb + 0 * slabB, plg + 0 * slabB, plB + 0 * slabB, wl + 0,
              3, (float*)l1, 0, 5, 0, M, sump, sqrp);
    run_mixed(28, plb + 2 * slabB, plg + 2 * slabB, plB + 2 * slabB, wl + 8,
              3, (float*)l2, 0, 6, 0, M, sump, sqrp);
    k_aggregate<<<M, 128>>>((const float*)m2, M);
    run_mixed(24, plb + 1 * slabB, plg + 1 * slabB, plB + 1 * slabB, wl + 4,
              4, (float*)l1, 1, 5, 1, M, sump, sqrp);
    run_mixed(32, plb + 3 * slabB, plg + 3 * slabB, plB + 3 * slabB, wl + 12,
              4, (float*)l2, 1, 6, 0, M, sump, sqrp);
    k_aggregate<<<M, 128>>>((const float*)l1, M);
    run_mixed(36, plb + 4 * slabB, plg + 4 * slabB, plB + 4 * slabB, wl + 16,
              5, (float*)l2, 1, 6, 1, M, sump, sqrp);

    // cat GEMM + batchnorm + relu + residual
    cudaMemsetAsync(sump, 0, 4 * DD * sizeof(float));
    cudaMemsetAsync(sqrp, 0, 4 * DD * sizeof(float));
    k_gemm_mma<<<dim3(4, (M + 127) / 128, 1), 256, SMEM_GEMM>>>(
        catb, M, 1, 0, (size_t)40 * SLAB);
    k_finalize<<<8, 256>>>(bng, bnb, M, 1);
    k_final<<<nsp, 256>>>(h, out, M);
}